// round 4
// baseline (speedup 1.0000x reference)
#include <cuda_runtime.h>
#include <math.h>

#define NS 100000
#define NF 50000
#define CC 128
#define HH 8
#define DD 16
#define EE 200000
#define TT 16

// ---------------- static scratch (no allocations allowed) ----------------
__device__ float g_xs[NS*CC], g_xf[NF*CC];     // current features
__device__ float g_ks[NS*CC], g_kf[NF*CC];     // K proj
__device__ float g_qs[NS*CC], g_qf[NF*CC];     // Q proj
__device__ float g_vs[NS*CC], g_vf[NF*CC];     // V proj
__device__ float g_kr[NS*CC], g_vr[NS*CC];     // per-relation transformed K/V (src side)
__device__ float g_ags[NS*CC], g_agf[NF*CC];   // aggregation (also encoder temp)
__device__ float g_lg[EE*HH];                  // edge logits / exp values
__device__ float g_mb[NS*HH], g_sb[NS*HH];     // segment max / sum

// ---------------- helpers ----------------
__device__ __forceinline__ void atomicMaxF(float* a, float v){
    int old = __float_as_int(*a);
    while (__int_as_float(old) < v){
        int assumed = old;
        old = atomicCAS((int*)a, assumed, __float_as_int(v));
        if (old == assumed) break;
    }
}

__device__ __forceinline__ void atomicAdd4(float* p, float x, float y, float z, float w){
#if defined(__CUDA_ARCH__) && (__CUDA_ARCH__ >= 900)
    float4 m; m.x = x; m.y = y; m.z = z; m.w = w;
    atomicAdd((float4*)p, m);
#else
    atomicAdd(p+0, x); atomicAdd(p+1, y); atomicAdd(p+2, z); atomicAdd(p+3, w);
#endif
}

__device__ __forceinline__ float gelu1(float x){
    float x3 = x*x*x;
    float t = tanhf(0.7978845608028654f*(x + 0.044715f*x3));
    return 0.5f*x*(1.f + t);
}

__global__ void fill_k(float* __restrict__ p, float v, int n){
    int i = blockIdx.x*blockDim.x + threadIdx.x;
    if (i < n) p[i] = v;
}

// fill mb with -1e30 and sb with 0 in one launch
__global__ void fill_ms_k(float* __restrict__ mb, float* __restrict__ sb, int n){
    int i = blockIdx.x*blockDim.x + threadIdx.x;
    if (i < n){ mb[i] = -1e30f; sb[i] = 0.f; }
}

// ---------------- encoder: mean-pool embeddings + relu ----------------
__global__ void encode_k(const int* __restrict__ tok, const float* __restrict__ emb,
                         float* __restrict__ out, int N){
    int g = blockIdx.x*blockDim.x + threadIdx.x;
    int w = g >> 5, lane = g & 31;
    if (w >= N) return;
    const int* tp = tok + w*TT;
    float ax=0.f, ay=0.f, az=0.f, aw=0.f;
    #pragma unroll
    for (int t=0; t<TT; t++){
        int tk = __ldg(tp + t);
        float4 v = __ldg(((const float4*)emb) + (size_t)tk*32 + lane);
        ax += v.x; ay += v.y; az += v.z; aw += v.w;
    }
    const float inv = 1.0f/(float)TT;
    float4 o;
    o.x = fmaxf(ax*inv, 0.f);
    o.y = fmaxf(ay*inv, 0.f);
    o.z = fmaxf(az*inv, 0.f);
    o.w = fmaxf(aw*inv, 0.f);
    ((float4*)out)[(size_t)w*32 + lane] = o;
}

// ---------------- single GEMM: Y[N,128] = act(X[N,128] @ W[128,128] + b) ----------------
// MODE 0: relu on output
// MODE 3: gelu on INPUT (X), gated-skip epilogue: Y = g*(gelu(X)@W + b) + (1-g)*Xold
template<int MODE>
__global__ void __launch_bounds__(256) gemm128_k(
    const float* __restrict__ X, const float* __restrict__ W,
    const float* __restrict__ B, float* __restrict__ Y,
    const float* __restrict__ Xold, const float* __restrict__ skip, int N)
{
    extern __shared__ float ws[];                   // 128x128 fp32 = 64KB
    for (int i = threadIdx.x; i < 4096; i += 256)
        ((float4*)ws)[i] = __ldg(((const float4*)W) + i);
    __syncthreads();

    int tx = threadIdx.x & 31;        // col group: cols tx*4..tx*4+3
    int ty = threadIdx.x >> 5;        // row group: 8 rows
    int row0 = blockIdx.x*64 + ty*8;

    float acc[8][4];
    #pragma unroll
    for (int i=0;i<8;i++){ acc[i][0]=acc[i][1]=acc[i][2]=acc[i][3]=0.f; }

    const float4* X4 = (const float4*)X;
    for (int k0 = 0; k0 < 32; k0++){
        float4 xv[8];
        #pragma unroll
        for (int i=0;i<8;i++){
            int r = row0 + i;
            xv[i] = (r < N) ? X4[(size_t)r*32 + k0] : make_float4(0.f,0.f,0.f,0.f);
            if (MODE == 3){
                xv[i].x = gelu1(xv[i].x); xv[i].y = gelu1(xv[i].y);
                xv[i].z = gelu1(xv[i].z); xv[i].w = gelu1(xv[i].w);
            }
        }
        #pragma unroll
        for (int kk=0; kk<4; kk++){
            float4 w4 = ((const float4*)ws)[(k0*4+kk)*32 + tx];
            #pragma unroll
            for (int i=0;i<8;i++){
                float xs = ((const float*)&xv[i])[kk];
                acc[i][0] += xs * w4.x;
                acc[i][1] += xs * w4.y;
                acc[i][2] += xs * w4.z;
                acc[i][3] += xs * w4.w;
            }
        }
    }

    float4 b4 = __ldg(((const float4*)B) + tx);
    float gate = 0.f;
    if (MODE == 3) gate = 1.f/(1.f + expf(-skip[0]));

    #pragma unroll
    for (int i=0;i<8;i++){
        int r = row0 + i;
        if (r >= N) break;
        float4 o;
        o.x = acc[i][0] + b4.x;
        o.y = acc[i][1] + b4.y;
        o.z = acc[i][2] + b4.z;
        o.w = acc[i][3] + b4.w;
        if (MODE == 0){
            o.x = fmaxf(o.x,0.f); o.y = fmaxf(o.y,0.f);
            o.z = fmaxf(o.z,0.f); o.w = fmaxf(o.w,0.f);
        } else if (MODE == 3){
            float4 xo = ((const float4*)Xold)[(size_t)r*32 + tx];
            float ig = 1.f - gate;
            o.x = gate*o.x + ig*xo.x;
            o.y = gate*o.y + ig*xo.y;
            o.z = gate*o.z + ig*xo.z;
            o.w = gate*o.w + ig*xo.w;
        }
        ((float4*)Y)[(size_t)r*32 + tx] = o;
    }
}

// ---------------- fused KQV GEMM: reads X once, produces 3 projections ----------------
__global__ void __launch_bounds__(512) gemm_kqv_k(
    const float* __restrict__ X,
    const float* __restrict__ WK, const float* __restrict__ BK,
    const float* __restrict__ WQ, const float* __restrict__ BQ,
    const float* __restrict__ WV, const float* __restrict__ BV,
    float* __restrict__ K, float* __restrict__ Q, float* __restrict__ V, int N)
{
    extern __shared__ float ws[];                   // 3 x 128x128 fp32 = 192KB
    float* wk = ws;
    float* wq = ws + 4096*4;   // 4096 float4 per matrix
    float* wv = ws + 8192*4;
    for (int i = threadIdx.x; i < 4096; i += 512){
        ((float4*)wk)[i] = __ldg(((const float4*)WK) + i);
        ((float4*)wq)[i] = __ldg(((const float4*)WQ) + i);
        ((float4*)wv)[i] = __ldg(((const float4*)WV) + i);
    }
    __syncthreads();

    int tx = threadIdx.x & 31;        // cols tx*4..tx*4+3
    int ty = threadIdx.x >> 5;        // 0..15, 4 rows each
    int row0 = blockIdx.x*64 + ty*4;

    float ak[4][4], aq[4][4], av[4][4];
    #pragma unroll
    for (int i=0;i<4;i++)
        #pragma unroll
        for (int j=0;j<4;j++){ ak[i][j]=0.f; aq[i][j]=0.f; av[i][j]=0.f; }

    const float4* X4 = (const float4*)X;
    for (int k0 = 0; k0 < 32; k0++){
        float4 xv[4];
        #pragma unroll
        for (int i=0;i<4;i++){
            int r = row0 + i;
            xv[i] = (r < N) ? X4[(size_t)r*32 + k0] : make_float4(0.f,0.f,0.f,0.f);
        }
        #pragma unroll
        for (int kk=0; kk<4; kk++){
            int wi = (k0*4+kk)*32 + tx;
            float4 k4 = ((const float4*)wk)[wi];
            float4 q4 = ((const float4*)wq)[wi];
            float4 v4 = ((const float4*)wv)[wi];
            #pragma unroll
            for (int i=0;i<4;i++){
                float xs = ((const float*)&xv[i])[kk];
                ak[i][0] += xs * k4.x; ak[i][1] += xs * k4.y;
                ak[i][2] += xs * k4.z; ak[i][3] += xs * k4.w;
                aq[i][0] += xs * q4.x; aq[i][1] += xs * q4.y;
                aq[i][2] += xs * q4.z; aq[i][3] += xs * q4.w;
                av[i][0] += xs * v4.x; av[i][1] += xs * v4.y;
                av[i][2] += xs * v4.z; av[i][3] += xs * v4.w;
            }
        }
    }

    float4 bk4 = __ldg(((const float4*)BK) + tx);
    float4 bq4 = __ldg(((const float4*)BQ) + tx);
    float4 bv4 = __ldg(((const float4*)BV) + tx);

    #pragma unroll
    for (int i=0;i<4;i++){
        int r = row0 + i;
        if (r >= N) break;
        float4 o;
        o.x = ak[i][0]+bk4.x; o.y = ak[i][1]+bk4.y; o.z = ak[i][2]+bk4.z; o.w = ak[i][3]+bk4.w;
        ((float4*)K)[(size_t)r*32 + tx] = o;
        o.x = aq[i][0]+bq4.x; o.y = aq[i][1]+bq4.y; o.z = aq[i][2]+bq4.z; o.w = aq[i][3]+bq4.w;
        ((float4*)Q)[(size_t)r*32 + tx] = o;
        o.x = av[i][0]+bv4.x; o.y = av[i][1]+bv4.y; o.z = av[i][2]+bv4.z; o.w = av[i][3]+bv4.w;
        ((float4*)V)[(size_t)r*32 + tx] = o;
    }
}

// ---------------- per-relation head transform: kr = k @ A[h], vr = v @ M[h] ----------------
__global__ void rel_transform_k(const float* __restrict__ K, const float* __restrict__ V,
                                const float* __restrict__ A, const float* __restrict__ M,
                                float* __restrict__ KR, float* __restrict__ VR, int N){
    __shared__ float sA[2048], sM[2048];
    for (int i = threadIdx.x; i < 2048; i += blockDim.x){
        sA[i] = __ldg(A + i);
        sM[i] = __ldg(M + i);
    }
    __syncthreads();
    int idx = blockIdx.x*blockDim.x + threadIdx.x;
    if (idx >= N*CC) return;
    int n = idx >> 7;
    int he = idx & 127;
    int h = he >> 4;
    int e = he & 15;
    const float* krow = K + (size_t)n*CC + h*DD;
    const float* vrow = V + (size_t)n*CC + h*DD;
    const float* Ah = sA + h*256;
    const float* Mh = sM + h*256;
    float ka = 0.f, va = 0.f;
    #pragma unroll
    for (int d=0; d<DD; d++){
        float kd = krow[d], vd = vrow[d];
        ka += kd * Ah[d*16 + e];
        va += vd * Mh[d*16 + e];
    }
    KR[idx] = ka;
    VR[idx] = va;
}

// ---------------- edge logits + segment max ----------------
__global__ void edge_logits_k(const float* __restrict__ Q, const float* __restrict__ KR,
                              const int* __restrict__ src, const int* __restrict__ dst,
                              const float* __restrict__ prel,
                              float* __restrict__ lg, float* __restrict__ mb, int E){
    int idx = blockIdx.x*blockDim.x + threadIdx.x;
    if (idx >= E*HH) return;
    int e = idx >> 3, h = idx & 7;
    int s = __ldg(src + e), d = __ldg(dst + e);
    const float4* q4 = (const float4*)(Q + (size_t)d*CC + h*DD);
    const float4* k4 = (const float4*)(KR + (size_t)s*CC + h*DD);
    float acc = 0.f;
    #pragma unroll
    for (int j=0; j<4; j++){
        float4 a = __ldg(q4 + j);
        float4 b = __ldg(k4 + j);
        acc += a.x*b.x + a.y*b.y + a.z*b.z + a.w*b.w;
    }
    float lgv = acc * __ldg(prel + h) * 0.25f;   // scale = 1/sqrt(16)
    lg[idx] = lgv;
    atomicMaxF(mb + (size_t)d*HH + h, lgv);
}

// ---------------- exp + segment sum ----------------
__global__ void edge_exp_k(float* __restrict__ lg, const float* __restrict__ mb,
                           const int* __restrict__ dst, float* __restrict__ sb, int E){
    int idx = blockIdx.x*blockDim.x + threadIdx.x;
    if (idx >= E*HH) return;
    int e = idx >> 3, h = idx & 7;
    int d = __ldg(dst + e);
    float ex = expf(lg[idx] - mb[(size_t)d*HH + h]);
    lg[idx] = ex;
    atomicAdd(sb + (size_t)d*HH + h, ex);
}

// ---------------- weighted message aggregation (one warp per edge, vec4 RED) ----------------
__global__ void edge_agg_k(const float* __restrict__ lg, const float* __restrict__ sb,
                           const float* __restrict__ VR,
                           const int* __restrict__ src, const int* __restrict__ dst,
                           float* __restrict__ AGG, int E){
    int g = blockIdx.x*blockDim.x + threadIdx.x;
    int e = g >> 5, lane = g & 31;
    if (e >= E) return;
    int s = __ldg(src + e), d = __ldg(dst + e);
    int h = lane >> 2;
    float alpha = lg[(size_t)e*HH + h] / (sb[(size_t)d*HH + h] + 1e-16f);
    float4 v = __ldg(((const float4*)VR) + (size_t)s*32 + lane);
    atomicAdd4(AGG + (size_t)d*CC + lane*4, v.x*alpha, v.y*alpha, v.z*alpha, v.w*alpha);
}

// ---------------- launch ----------------
static inline int cdiv(int a, int b){ return (a + b - 1)/b; }

extern "C" void kernel_launch(void* const* d_in, const int* in_sizes, int n_in,
                              void* d_out, int out_size){
    const int* tok_s = (const int*)d_in[0];
    const int* tok_f = (const int*)d_in[1];
    const int* esrc[3] = {(const int*)d_in[2], (const int*)d_in[4], (const int*)d_in[6]};
    const int* edst[3] = {(const int*)d_in[3], (const int*)d_in[5], (const int*)d_in[7]};
    const float* emb   = (const float*)d_in[8];
    const float* lin_w = (const float*)d_in[9];
    const float* lin_b = (const float*)d_in[10];
    const float* kw = (const float*)d_in[11]; const float* kbi = (const float*)d_in[12];
    const float* qw = (const float*)d_in[13]; const float* qbi = (const float*)d_in[14];
    const float* vw = (const float*)d_in[15]; const float* vbi = (const float*)d_in[16];
    const float* aw = (const float*)d_in[17]; const float* abi = (const float*)d_in[18];
    const float* skip  = (const float*)d_in[19];
    const float* a_rel = (const float*)d_in[20];
    const float* m_rel = (const float*)d_in[21];
    const float* p_rel = (const float*)d_in[22];
    float* out = (float*)d_out;

    float *xs,*xf,*ks,*kf,*qs,*qf,*vs,*vf,*kr,*vr,*ags,*agf,*lg,*mb,*sb;
    cudaGetSymbolAddress((void**)&xs, g_xs);  cudaGetSymbolAddress((void**)&xf, g_xf);
    cudaGetSymbolAddress((void**)&ks, g_ks);  cudaGetSymbolAddress((void**)&kf, g_kf);
    cudaGetSymbolAddress((void**)&qs, g_qs);  cudaGetSymbolAddress((void**)&qf, g_qf);
    cudaGetSymbolAddress((void**)&vs, g_vs);  cudaGetSymbolAddress((void**)&vf, g_vf);
    cudaGetSymbolAddress((void**)&kr, g_kr);  cudaGetSymbolAddress((void**)&vr, g_vr);
    cudaGetSymbolAddress((void**)&ags, g_ags);cudaGetSymbolAddress((void**)&agf, g_agf);
    cudaGetSymbolAddress((void**)&lg, g_lg);
    cudaGetSymbolAddress((void**)&mb, g_mb);  cudaGetSymbolAddress((void**)&sb, g_sb);

    const int SMEM1 = 65536;       // single-weight GEMM
    const int SMEM3 = 3*65536;     // fused KQV GEMM (192KB < 227KB cap)
    cudaFuncSetAttribute(gemm128_k<0>, cudaFuncAttributeMaxDynamicSharedMemorySize, SMEM1);
    cudaFuncSetAttribute(gemm128_k<3>, cudaFuncAttributeMaxDynamicSharedMemorySize, SMEM1);
    cudaFuncSetAttribute(gemm_kqv_k,   cudaFuncAttributeMaxDynamicSharedMemorySize, SMEM3);

    // encoder: mean-pool -> relu -> linear -> relu  (agg buffers as temp)
    encode_k<<<cdiv(NS,8), 256>>>(tok_s, emb, ags, NS);
    encode_k<<<cdiv(NF,8), 256>>>(tok_f, emb, agf, NF);
    gemm128_k<0><<<cdiv(NS,64), 256, SMEM1>>>(ags, lin_w,        lin_b,      xs, nullptr, nullptr, NS);
    gemm128_k<0><<<cdiv(NF,64), 256, SMEM1>>>(agf, lin_w+CC*CC,  lin_b+CC,   xf, nullptr, nullptr, NF);

    int   Nn[2]  = {NS, NF};
    float* xb[2] = {xs, xf};
    float* kB[2] = {ks, kf};
    float* qB[2] = {qs, qf};
    float* vB[2] = {vs, vf};
    float* agB[2]= {ags, agf};
    const int rel_st[3] = {0,0,1};
    const int rel_dt[3] = {0,1,0};

    for (int l=0; l<2; l++){
        // fused K/Q/V projections (X read once per type)
        for (int t=0; t<2; t++){
            int wi = (l*2+t)*CC*CC, bi = (l*2+t)*CC;
            gemm_kqv_k<<<cdiv(Nn[t],64), 512, SMEM3>>>(xb[t],
                kw+wi, kbi+bi, qw+wi, qbi+bi, vw+wi, vbi+bi,
                kB[t], qB[t], vB[t], Nn[t]);
        }
        // zero aggregation
        fill_k<<<cdiv(NS*CC,256),256>>>(ags, 0.f, NS*CC);
        fill_k<<<cdiv(NF*CC,256),256>>>(agf, 0.f, NF*CC);

        for (int r=0; r<3; r++){
            int st = rel_st[r], dt = rel_dt[r];
            int Nsrc = Nn[st], Ndst = Nn[dt];
            rel_transform_k<<<cdiv(Nsrc*CC,256),256>>>(kB[st], vB[st],
                a_rel + (l*3+r)*HH*DD*DD, m_rel + (l*3+r)*HH*DD*DD, kr, vr, Nsrc);
            fill_ms_k<<<cdiv(Ndst*HH,256),256>>>(mb, sb, Ndst*HH);
            edge_logits_k<<<cdiv(EE*HH,256),256>>>(qB[dt], kr, esrc[r], edst[r],
                p_rel + (l*3+r)*HH, lg, mb, EE);
            edge_exp_k<<<cdiv(EE*HH,256),256>>>(lg, mb, edst[r], sb, EE);
            edge_agg_k<<<cdiv(EE*32,256),256>>>(lg, sb, vr, esrc[r], edst[r], agB[dt], EE);
        }

        // output projection (gelu fused on input) + gated skip
        for (int t=0; t<2; t++){
            float* dest = (l==1) ? (t==0 ? out : out + (size_t)NS*CC) : xb[t];
            gemm128_k<3><<<cdiv(Nn[t],64),256,SMEM1>>>(agB[t], aw+(l*2+t)*CC*CC,
                abi+(l*2+t)*CC, dest, xb[t], skip + l*2+t, Nn[t]);
        }
    }
}

// round 7
// speedup vs baseline: 1.3906x; 1.3906x over previous
#include <cuda_runtime.h>
#include <math.h>

#define NS 100000
#define NF 50000
#define CC 128
#define HH 8
#define DD 16
#define EE 200000
#define TT 16

// ---------------- static scratch (no allocations allowed) ----------------
__device__ float g_xs[NS*CC], g_xf[NF*CC];     // current features
__device__ float g_ks[NS*CC], g_kf[NF*CC];     // K proj
__device__ float g_qs[NS*CC], g_qf[NF*CC];     // Q proj
__device__ float g_vs[NS*CC], g_vf[NF*CC];     // V proj
__device__ float g_kr[NS*CC], g_vr[NS*CC];     // per-relation transformed K/V (src side)
__device__ float g_ags[NS*CC], g_agf[NF*CC];   // aggregation (also encoder temp)
__device__ float g_lg[EE*HH];                  // edge logits / exp values
__device__ float g_mb[NS*HH], g_sb[NS*HH];     // segment max / sum

// ---------------- helpers ----------------
__device__ __forceinline__ void atomicMaxF(float* a, float v){
    int old = __float_as_int(*a);
    while (__int_as_float(old) < v){
        int assumed = old;
        old = atomicCAS((int*)a, assumed, __float_as_int(v));
        if (old == assumed) break;
    }
}

__device__ __forceinline__ void atomicAdd4(float* p, float x, float y, float z, float w){
#if defined(__CUDA_ARCH__) && (__CUDA_ARCH__ >= 900)
    float4 m; m.x = x; m.y = y; m.z = z; m.w = w;
    atomicAdd((float4*)p, m);
#else
    atomicAdd(p+0, x); atomicAdd(p+1, y); atomicAdd(p+2, z); atomicAdd(p+3, w);
#endif
}

__device__ __forceinline__ float gelu1(float x){
    float x3 = x*x*x;
    float t = tanhf(0.7978845608028654f*(x + 0.044715f*x3));
    return 0.5f*x*(1.f + t);
}

__global__ void fill_k(float* __restrict__ p, float v, int n){
    int i = blockIdx.x*blockDim.x + threadIdx.x;
    if (i < n) p[i] = v;
}

__global__ void fill_ms_k(float* __restrict__ mb, float* __restrict__ sb, int n){
    int i = blockIdx.x*blockDim.x + threadIdx.x;
    if (i < n){ mb[i] = -1e30f; sb[i] = 0.f; }
}

// ---------------- encoder: mean-pool embeddings + relu ----------------
__global__ void encode_k(const int* __restrict__ tok, const float* __restrict__ emb,
                         float* __restrict__ out, int N){
    int g = blockIdx.x*blockDim.x + threadIdx.x;
    int w = g >> 5, lane = g & 31;
    if (w >= N) return;
    const int* tp = tok + w*TT;
    float ax=0.f, ay=0.f, az=0.f, aw=0.f;
    #pragma unroll
    for (int t=0; t<TT; t++){
        int tk = __ldg(tp + t);
        float4 v = __ldg(((const float4*)emb) + (size_t)tk*32 + lane);
        ax += v.x; ay += v.y; az += v.z; aw += v.w;
    }
    const float inv = 1.0f/(float)TT;
    float4 o;
    o.x = fmaxf(ax*inv, 0.f);
    o.y = fmaxf(ay*inv, 0.f);
    o.z = fmaxf(az*inv, 0.f);
    o.w = fmaxf(aw*inv, 0.f);
    ((float4*)out)[(size_t)w*32 + lane] = o;
}

// ---------------- pipelined GEMM: Y[N,128] = act(op(X)[N,128] @ W[128,128] + b) ----------------
// MODE 0: relu on output
// MODE 1: bias only
// MODE 3: gelu applied to X at staging time; gated-skip epilogue
// 64 rows/block, 256 threads. W (64KB) + double-buffered X stage (2x4KB) in smem.
// X staged one stage (4 k-quads) ahead: LDG -> [gelu] -> STS -> sync -> compute from smem.
template<int MODE>
__global__ void __launch_bounds__(256, 3) gemm128p_k(
    const float* __restrict__ X, const float* __restrict__ W,
    const float* __restrict__ B, float* __restrict__ Y,
    const float* __restrict__ Xold, const float* __restrict__ skip, int N)
{
    extern __shared__ float smem[];
    float4* ws4 = (float4*)smem;               // 4096 float4 = 64KB
    float4* xb4 = (float4*)(smem + 16384);     // 2 * 256 float4 = 8KB

    int tid = threadIdx.x;
    for (int i = tid; i < 4096; i += 256)
        ws4[i] = __ldg(((const float4*)W) + i);

    int tx = tid & 31;            // output col group: cols tx*4..tx*4+3
    int ty = tid >> 5;            // row group: 8 rows
    int rlo = ty*8;               // local row base
    int row0 = blockIdx.x*64 + rlo;

    // copy role: one float4 per thread per stage
    int crow = tid >> 2;          // 0..63 local row
    int ckk  = tid & 3;           // 0..3  k-quad within stage
    int grow = blockIdx.x*64 + crow;
    if (grow >= N) grow = N-1;    // clamp; duplicate data discarded at epilogue
    const float4* Xg = (const float4*)X + (size_t)grow*32 + ckk;

    float acc[8][4];
    #pragma unroll
    for (int i=0;i<8;i++){ acc[i][0]=acc[i][1]=acc[i][2]=acc[i][3]=0.f; }

    float4 cur = __ldg(Xg);       // stage 0 prefetch
    __syncthreads();              // W ready

    #pragma unroll 1
    for (int s=0; s<8; s++){
        float4 nxt;
        if (s < 7) nxt = __ldg(Xg + 4*(s+1));
        if (MODE == 3){
            cur.x = gelu1(cur.x); cur.y = gelu1(cur.y);
            cur.z = gelu1(cur.z); cur.w = gelu1(cur.w);
        }
        float4* buf = xb4 + (s&1)*256;
        buf[ckk*64 + crow] = cur;
        __syncthreads();

        #pragma unroll
        for (int kk=0; kk<4; kk++){
            int k0 = s*4 + kk;                       // global k-quad 0..31
            float4 w0 = ws4[(k0*4+0)*32 + tx];
            float4 w1 = ws4[(k0*4+1)*32 + tx];
            float4 w2 = ws4[(k0*4+2)*32 + tx];
            float4 w3 = ws4[(k0*4+3)*32 + tx];
            #pragma unroll
            for (int i=0;i<8;i++){
                float4 xv = buf[kk*64 + rlo + i];    // warp-broadcast LDS
                acc[i][0] += xv.x*w0.x + xv.y*w1.x + xv.z*w2.x + xv.w*w3.x;
                acc[i][1] += xv.x*w0.y + xv.y*w1.y + xv.z*w2.y + xv.w*w3.y;
                acc[i][2] += xv.x*w0.z + xv.y*w1.z + xv.z*w2.z + xv.w*w3.z;
                acc[i][3] += xv.x*w0.w + xv.y*w1.w + xv.z*w2.w + xv.w*w3.w;
            }
        }
        __syncthreads();
        cur = nxt;
    }

    float4 b4 = __ldg(((const float4*)B) + tx);
    float gate = 0.f;
    if (MODE == 3) gate = 1.f/(1.f + expf(-skip[0]));

    #pragma unroll
    for (int i=0;i<8;i++){
        int r = row0 + i;
        if (r >= N) break;
        float4 o;
        o.x = acc[i][0] + b4.x;
        o.y = acc[i][1] + b4.y;
        o.z = acc[i][2] + b4.z;
        o.w = acc[i][3] + b4.w;
        if (MODE == 0){
            o.x = fmaxf(o.x,0.f); o.y = fmaxf(o.y,0.f);
            o.z = fmaxf(o.z,0.f); o.w = fmaxf(o.w,0.f);
        } else if (MODE == 3){
            float4 xo = ((const float4*)Xold)[(size_t)r*32 + tx];
            float ig = 1.f - gate;
            o.x = gate*o.x + ig*xo.x;
            o.y = gate*o.y + ig*xo.y;
            o.z = gate*o.z + ig*xo.z;
            o.w = gate*o.w + ig*xo.w;
        }
        ((float4*)Y)[(size_t)r*32 + tx] = o;
    }
}

// ---------------- per-relation head transform: kr = k @ A[h], vr = v @ M[h] ----------------
__global__ void rel_transform_k(const float* __restrict__ K, const float* __restrict__ V,
                                const float* __restrict__ A, const float* __restrict__ M,
                                float* __restrict__ KR, float* __restrict__ VR, int N){
    __shared__ float sA[2048], sM[2048];
    for (int i = threadIdx.x; i < 2048; i += blockDim.x){
        sA[i] = __ldg(A + i);
        sM[i] = __ldg(M + i);
    }
    __syncthreads();
    int idx = blockIdx.x*blockDim.x + threadIdx.x;
    if (idx >= N*CC) return;
    int n = idx >> 7;
    int he = idx & 127;
    int h = he >> 4;
    int e = he & 15;
    const float* krow = K + (size_t)n*CC + h*DD;
    const float* vrow = V + (size_t)n*CC + h*DD;
    const float* Ah = sA + h*256;
    const float* Mh = sM + h*256;
    float ka = 0.f, va = 0.f;
    #pragma unroll
    for (int d=0; d<DD; d++){
        float kd = krow[d], vd = vrow[d];
        ka += kd * Ah[d*16 + e];
        va += vd * Mh[d*16 + e];
    }
    KR[idx] = ka;
    VR[idx] = va;
}

// ---------------- edge logits + segment max ----------------
__global__ void edge_logits_k(const float* __restrict__ Q, const float* __restrict__ KR,
                              const int* __restrict__ src, const int* __restrict__ dst,
                              const float* __restrict__ prel,
                              float* __restrict__ lg, float* __restrict__ mb, int E){
    int idx = blockIdx.x*blockDim.x + threadIdx.x;
    if (idx >= E*HH) return;
    int e = idx >> 3, h = idx & 7;
    int s = __ldg(src + e), d = __ldg(dst + e);
    const float4* q4 = (const float4*)(Q + (size_t)d*CC + h*DD);
    const float4* k4 = (const float4*)(KR + (size_t)s*CC + h*DD);
    float acc = 0.f;
    #pragma unroll
    for (int j=0; j<4; j++){
        float4 a = __ldg(q4 + j);
        float4 b = __ldg(k4 + j);
        acc += a.x*b.x + a.y*b.y + a.z*b.z + a.w*b.w;
    }
    float lgv = acc * __ldg(prel + h) * 0.25f;   // scale = 1/sqrt(16)
    lg[idx] = lgv;
    atomicMaxF(mb + (size_t)d*HH + h, lgv);
}

// ---------------- exp + segment sum ----------------
__global__ void edge_exp_k(float* __restrict__ lg, const float* __restrict__ mb,
                           const int* __restrict__ dst, float* __restrict__ sb, int E){
    int idx = blockIdx.x*blockDim.x + threadIdx.x;
    if (idx >= E*HH) return;
    int e = idx >> 3, h = idx & 7;
    int d = __ldg(dst + e);
    float ex = expf(lg[idx] - mb[(size_t)d*HH + h]);
    lg[idx] = ex;
    atomicAdd(sb + (size_t)d*HH + h, ex);
}

// ---------------- weighted message aggregation (one warp per edge, vec4 RED) ----------------
__global__ void edge_agg_k(const float* __restrict__ lg, const float* __restrict__ sb,
                           const float* __restrict__ VR,
                           const int* __restrict__ src, const int* __restrict__ dst,
                           float* __restrict__ AGG, int E){
    int g = blockIdx.x*blockDim.x + threadIdx.x;
    int e = g >> 5, lane = g & 31;
    if (e >= E) return;
    int s = __ldg(src + e), d = __ldg(dst + e);
    int h = lane >> 2;
    float alpha = lg[(size_t)e*HH + h] / (sb[(size_t)d*HH + h] + 1e-16f);
    float4 v = __ldg(((const float4*)VR) + (size_t)s*32 + lane);
    atomicAdd4(AGG + (size_t)d*CC + lane*4, v.x*alpha, v.y*alpha, v.z*alpha, v.w*alpha);
}

// ---------------- launch ----------------
static inline int cdiv(int a, int b){ return (a + b - 1)/b; }

extern "C" void kernel_launch(void* const* d_in, const int* in_sizes, int n_in,
                              void* d_out, int out_size){
    const int* tok_s = (const int*)d_in[0];
    const int* tok_f = (const int*)d_in[1];
    const int* esrc[3] = {(const int*)d_in[2], (const int*)d_in[4], (const int*)d_in[6]};
    const int* edst[3] = {(const int*)d_in[3], (const int*)d_in[5], (const int*)d_in[7]};
    const float* emb   = (const float*)d_in[8];
    const float* lin_w = (const float*)d_in[9];
    const float* lin_b = (const float*)d_in[10];
    const float* kw = (const float*)d_in[11]; const float* kbi = (const float*)d_in[12];
    const float* qw = (const float*)d_in[13]; const float* qbi = (const float*)d_in[14];
    const float* vw = (const float*)d_in[15]; const float* vbi = (const float*)d_in[16];
    const float* aw = (const float*)d_in[17]; const float* abi = (const float*)d_in[18];
    const float* skip  = (const float*)d_in[19];
    const float* a_rel = (const float*)d_in[20];
    const float* m_rel = (const float*)d_in[21];
    const float* p_rel = (const float*)d_in[22];
    float* out = (float*)d_out;

    float *xs,*xf,*ks,*kf,*qs,*qf,*vs,*vf,*kr,*vr,*ags,*agf,*lg,*mb,*sb;
    cudaGetSymbolAddress((void**)&xs, g_xs);  cudaGetSymbolAddress((void**)&xf, g_xf);
    cudaGetSymbolAddress((void**)&ks, g_ks);  cudaGetSymbolAddress((void**)&kf, g_kf);
    cudaGetSymbolAddress((void**)&qs, g_qs);  cudaGetSymbolAddress((void**)&qf, g_qf);
    cudaGetSymbolAddress((void**)&vs, g_vs);  cudaGetSymbolAddress((void**)&vf, g_vf);
    cudaGetSymbolAddress((void**)&kr, g_kr);  cudaGetSymbolAddress((void**)&vr, g_vr);
    cudaGetSymbolAddress((void**)&ags, g_ags);cudaGetSymbolAddress((void**)&agf, g_agf);
    cudaGetSymbolAddress((void**)&lg, g_lg);
    cudaGetSymbolAddress((void**)&mb, g_mb);  cudaGetSymbolAddress((void**)&sb, g_sb);

    const int SMEM = 73728;   // 64KB W + 8KB X double-buffer
    cudaFuncSetAttribute(gemm128p_k<0>, cudaFuncAttributeMaxDynamicSharedMemorySize, SMEM);
    cudaFuncSetAttribute(gemm128p_k<1>, cudaFuncAttributeMaxDynamicSharedMemorySize, SMEM);
    cudaFuncSetAttribute(gemm128p_k<3>, cudaFuncAttributeMaxDynamicSharedMemorySize, SMEM);

    // encoder: mean-pool -> relu -> linear -> relu  (agg buffers as temp)
    encode_k<<<cdiv(NS,8), 256>>>(tok_s, emb, ags, NS);
    encode_k<<<cdiv(NF,8), 256>>>(tok_f, emb, agf, NF);
    gemm128p_k<0><<<cdiv(NS,64), 256, SMEM>>>(ags, lin_w,       lin_b,    xs, nullptr, nullptr, NS);
    gemm128p_k<0><<<cdiv(NF,64), 256, SMEM>>>(agf, lin_w+CC*CC, lin_b+CC, xf, nullptr, nullptr, NF);

    int   Nn[2]  = {NS, NF};
    float* xb[2] = {xs, xf};
    float* kB[2] = {ks, kf};
    float* qB[2] = {qs, qf};
    float* vB[2] = {vs, vf};
    float* agB[2]= {ags, agf};
    const int rel_st[3] = {0,0,1};
    const int rel_dt[3] = {0,1,0};

    for (int l=0; l<2; l++){
        // K/Q/V projections (X stays L2-resident across the 3 launches)
        for (int t=0; t<2; t++){
            int wi = (l*2+t)*CC*CC, bi = (l*2+t)*CC;
            int gb = cdiv(Nn[t],64);
            gemm128p_k<1><<<gb,256,SMEM>>>(xb[t], kw+wi, kbi+bi, kB[t], nullptr, nullptr, Nn[t]);
            gemm128p_k<1><<<gb,256,SMEM>>>(xb[t], qw+wi, qbi+bi, qB[t], nullptr, nullptr, Nn[t]);
            gemm128p_k<1><<<gb,256,SMEM>>>(xb[t], vw+wi, vbi+bi, vB[t], nullptr, nullptr, Nn[t]);
        }
        // zero aggregation
        fill_k<<<cdiv(NS*CC,256),256>>>(ags, 0.f, NS*CC);
        fill_k<<<cdiv(NF*CC,256),256>>>(agf, 0.f, NF*CC);

        for (int r=0; r<3; r++){
            int st = rel_st[r], dt = rel_dt[r];
            int Nsrc = Nn[st], Ndst = Nn[dt];
            rel_transform_k<<<cdiv(Nsrc*CC,256),256>>>(kB[st], vB[st],
                a_rel + (l*3+r)*HH*DD*DD, m_rel + (l*3+r)*HH*DD*DD, kr, vr, Nsrc);
            fill_ms_k<<<cdiv(Ndst*HH,256),256>>>(mb, sb, Ndst*HH);
            edge_logits_k<<<cdiv(EE*HH,256),256>>>(qB[dt], kr, esrc[r], edst[r],
                p_rel + (l*3+r)*HH, lg, mb, EE);
            edge_exp_k<<<cdiv(EE*HH,256),256>>>(lg, mb, edst[r], sb, EE);
            edge_agg_k<<<cdiv(EE*32,256),256>>>(lg, sb, vr, esrc[r], edst[r], agB[dt], EE);
        }

        // output projection (gelu applied at staging) + gated skip
        for (int t=0; t<2; t++){
            float* dest = (l==1) ? (t==0 ? out : out + (size_t)NS*CC) : xb[t];
            gemm128p_k<3><<<cdiv(Nn[t],64),256,SMEM>>>(agB[t], aw+(l*2+t)*CC*CC,
                abi+(l*2+t)*CC, dest, xb[t], skip + l*2+t, Nn[t]);
        }
    }
}